// round 15
// baseline (speedup 1.0000x reference)
#include <cuda_runtime.h>
#include <cuda_bf16.h>
#include <math.h>

#define Nn 10000
#define Ee 320000
#define Dd 256
#define Hh 4
#define BN_EPS 1e-5f
#define MROWS 10112   // 79 * 128 padded rows
#define SCANB 40      // scan blocks (40*256 >= Nn)

// ---------------- scratch (device globals; zero-initialized at load, re-zeroed by
// the tail of each run so every graph replay starts from the same state) ----------
__device__ int   g_cin[Nn];
__device__ int   g_cout[Nn];
__device__ int   g_off[Nn + 1];
__device__ int   g_fill[Nn];
__device__ int   g_csrc[Ee];
__device__ int   g_bsum[SCANB];
__device__ int   g_flag;
__device__ int   g_maxdeg;
__device__ float g_sumexp;
__device__ float g_ex[Nn];
__device__ __nv_bfloat16 g_mVh[MROWS * Dd];  // bf16 center-scaled mV (row-major)
__device__ float g_q[MROWS * Dd];            // fp32 q
__device__ __nv_bfloat16 g_kh[MROWS * Dd];   // bf16 k
__device__ __nv_bfloat16 g_vh[MROWS * Dd];   // bf16 vv
__device__ __nv_bfloat16 g_wv[MROWS * Dd];   // bf16 normalized wv (row-major)
__device__ float g_o[MROWS * Dd];
__device__ __nv_bfloat16 g_Wth[4 * Dd * Dd]; // bf16 transposed weights [z][n][k]
__device__ float g_bnsum[Dd];
__device__ float g_bnss[Dd];

// ---------------- side stream + events (created at load) ----------------
struct SideStream {
    cudaStream_t s2;
    cudaEvent_t ev_scan, ev_s2;
    SideStream() {
        cudaStreamCreateWithFlags(&s2, cudaStreamNonBlocking);
        cudaEventCreateWithFlags(&ev_scan, cudaEventDisableTiming);
        cudaEventCreateWithFlags(&ev_s2, cudaEventDisableTiming);
    }
};
static SideStream g_ss;

// ---------------- 1: fused count + scan + softmax prep (flag-phase sync) ----------
// Counters (g_cin/g_cout/g_flag/g_maxdeg/g_sumexp) are zero on entry: .bss zero on
// the first call, re-zeroed by k_se's tail on every subsequent graph replay.
__global__ void __launch_bounds__(256) k_scan(const int* __restrict__ src,
                                              const int* __restrict__ dst) {
    __shared__ int wsum[8];
    __shared__ int wmax[8];
    __shared__ float wred[8];
    __shared__ int pre_s;
    int t = threadIdx.x;
    int lane = t & 31, w = t >> 5;
    int bid = blockIdx.x;

    // ---- phase 0: degree histograms (grid-stride, fire-and-forget REDs) ----
    for (int e = bid * 256 + t; e < Ee; e += SCANB * 256) {
        atomicAdd(&g_cout[src[e]], 1);
        atomicAdd(&g_cin[dst[e]], 1);
    }
    __syncthreads();
    if (t == 0) {
        __threadfence();
        atomicAdd(&g_flag, 1);
        while (atomicAdd(&g_flag, 0) < SCANB) { }   // all 40 blocks co-resident
    }
    __syncthreads();

    // ---- phase 1: per-block scan of cin + block max(deg) ----
    int n = bid * 256 + t;
    int ci = (n < Nn) ? g_cin[n] : 0;
    int co = (n < Nn) ? g_cout[n] : 0;
    int deg = ci + co;

    int x = ci;
#pragma unroll
    for (int o = 1; o < 32; o <<= 1) {
        int y = __shfl_up_sync(0xffffffffu, x, o);
        if (lane >= o) x += y;
    }
    int m = deg;
#pragma unroll
    for (int o = 16; o > 0; o >>= 1) m = max(m, __shfl_xor_sync(0xffffffffu, m, o));

    if (lane == 31) wsum[w] = x;
    if (lane == 0) wmax[w] = m;
    __syncthreads();
    if (w == 0) {
        int v = (lane < 8) ? wsum[lane] : 0;
#pragma unroll
        for (int o = 1; o < 8; o <<= 1) {
            int y = __shfl_up_sync(0xffffffffu, v, o);
            if (lane >= o) v += y;
        }
        if (lane < 8) wsum[lane] = v;
        int mm = (lane < 8) ? wmax[lane] : 0;
#pragma unroll
        for (int o = 4; o > 0; o >>= 1) mm = max(mm, __shfl_xor_sync(0xffffffffu, mm, o));
        if (lane == 0) {
            atomicMax(&g_maxdeg, mm);
            g_bsum[bid] = wsum[7];
            __threadfence();
            atomicAdd(&g_flag, 1);
        }
    }
    if (t == 0) {
        while (atomicAdd(&g_flag, 0) < 2 * SCANB) { }
    }
    __syncthreads();

    // ---- phase 2: global prefix + offsets + exp + sumexp ----
    if (t < 32) {
        int v = (t < bid) ? g_bsum[t] : 0;
        if (t + 32 < bid) v += g_bsum[t + 32];
#pragma unroll
        for (int o = 16; o > 0; o >>= 1) v += __shfl_xor_sync(0xffffffffu, v, o);
        if (t == 0) pre_s = v;
    }
    __syncthreads();

    int wpre = (w > 0) ? wsum[w - 1] : 0;
    int off = pre_s + wpre + x - ci;
    int maxdeg = g_maxdeg;
    float ex = 0.0f;
    if (n < Nn) {
        g_off[n] = off;
        g_fill[n] = off;
        ex = expf((float)(deg - maxdeg));
        g_ex[n] = ex;
    }
    if (bid == 0 && t == 0) g_off[Nn] = Ee;

    float s = ex;
#pragma unroll
    for (int o = 16; o > 0; o >>= 1) s += __shfl_xor_sync(0xffffffffu, s, o);
    if (lane == 0) wred[w] = s;
    __syncthreads();
    if (w == 0) {
        float v = (lane < 8) ? wred[lane] : 0.0f;
#pragma unroll
        for (int o = 4; o > 0; o >>= 1) v += __shfl_xor_sync(0xffffffffu, v, o);
        if (lane == 0) atomicAdd(&g_sumexp, v);
    }
}

// ---------------- 1c: scatter src ids into CSR order ----------------
__global__ void k_scatter(const int* __restrict__ src, const int* __restrict__ dst) {
    int e = blockIdx.x * blockDim.x + threadIdx.x;
    if (e < Ee) {
        int d = dst[e];
        int pos = atomicAdd(&g_fill[d], 1);
        g_csrc[pos] = src[e];
    }
}

// ---------------- 2: fused prep — weight transpose (blocks 0..255) + mv (rest) -----
__global__ void __launch_bounds__(256) k_prep(const float* __restrict__ v,
                                              const float* __restrict__ WQ,
                                              const float* __restrict__ WK,
                                              const float* __restrict__ WV,
                                              const float* __restrict__ Wo) {
    int b = blockIdx.x;
    if (b < 256) {
        __shared__ float tl[32][33];
        int z = b >> 6;
        int idx = b & 63;
        int k0 = (idx & 7) * 32, n0 = (idx >> 3) * 32;
        const float* W = (z == 0) ? WQ : (z == 1) ? WK : (z == 2) ? WV : Wo;
        int tx = threadIdx.x & 31, ty = threadIdx.x >> 5;
#pragma unroll
        for (int j = 0; j < 32; j += 8)
            tl[ty + j][tx] = W[(size_t)(k0 + ty + j) * Dd + n0 + tx];
        __syncthreads();
#pragma unroll
        for (int j = 0; j < 32; j += 8)
            g_Wth[(size_t)z * Dd * Dd + (size_t)(n0 + ty + j) * Dd + k0 + tx] =
                __float2bfloat16(tl[tx][ty + j]);
    } else {
        int i4 = (b - 256) * 256 + threadIdx.x;
        if (i4 >= Nn * Dd / 4) return;
        int n = i4 >> 6;
        float c = g_ex[n] / g_sumexp;
        float4 a = ((const float4*)v)[i4];
        __nv_bfloat162 p0 = __float22bfloat162_rn(make_float2(a.x * c, a.y * c));
        __nv_bfloat162 p1 = __float22bfloat162_rn(make_float2(a.z * c, a.w * c));
        __nv_bfloat162* o = (__nv_bfloat162*)g_mVh;
        o[i4 * 2]     = p0;
        o[i4 * 2 + 1] = p1;
    }
}

// ---------------- cp.async helpers ----------------
__device__ __forceinline__ void cpa16(void* s, const void* g) {
    unsigned sa = (unsigned)__cvta_generic_to_shared(s);
    asm volatile("cp.async.ca.shared.global [%0], [%1], 16;" :: "r"(sa), "l"(g));
}
__device__ __forceinline__ void cp_commit() { asm volatile("cp.async.commit_group;"); }
__device__ __forceinline__ void cp_wait1() { asm volatile("cp.async.wait_group 1;"); }

__device__ __forceinline__ void mma16(float* c, const unsigned* a, const unsigned* b) {
    asm volatile(
        "mma.sync.aligned.m16n8k16.row.col.f32.bf16.bf16.f32 "
        "{%0,%1,%2,%3},{%4,%5,%6,%7},{%8,%9},{%0,%1,%2,%3};"
        : "+f"(c[0]), "+f"(c[1]), "+f"(c[2]), "+f"(c[3])
        : "r"(a[0]), "r"(a[1]), "r"(a[2]), "r"(a[3]), "r"(b[0]), "r"(b[1]));
}

// ---------------- 4: bf16 tensor-core GEMM, 3-stage cp.async ------
template <int MODE>
__global__ void __launch_bounds__(256) k_gemm_bf16(
    const float* __restrict__ ba, const float* __restrict__ bb, const float* __restrict__ bc) {
    __shared__ __nv_bfloat16 As[3][128 * 40];
    __shared__ __nv_bfloat16 Bs[3][128 * 40];

    const int zsel = (MODE == 0) ? blockIdx.z : 3;
    const __nv_bfloat16* A = (MODE == 0) ? g_mVh : g_wv;
    const __nv_bfloat16* B = g_Wth + (size_t)zsel * Dd * Dd;
    const float* bias = (MODE == 1) ? ba : (zsel == 0) ? ba : (zsel == 1) ? bb : bc;

    const int tid = threadIdx.x;
    const int lane = tid & 31;
    const int warp = tid >> 5;
    const int wm = warp & 1;
    const int wn = warp >> 1;
    const int gid = lane >> 2;
    const int tig = lane & 3;
    const int bm = blockIdx.y * 128;
    const int bn = blockIdx.x * 128;

    const int lrow0 = tid >> 2;
    const int lcol0 = (tid & 3) * 8;
    const int lrow1 = (tid + 256) >> 2;
    const int lcol1 = lcol0;

    float acc[4][4][4];
#pragma unroll
    for (int i = 0; i < 4; i++)
#pragma unroll
        for (int j = 0; j < 4; j++)
#pragma unroll
            for (int q = 0; q < 4; q++) acc[i][j][q] = 0.0f;

#pragma unroll
    for (int st = 0; st < 2; st++) {
        int k0 = st * 32;
        cpa16(&As[st][lrow0 * 40 + lcol0], A + (size_t)(bm + lrow0) * Dd + k0 + lcol0);
        cpa16(&As[st][lrow1 * 40 + lcol1], A + (size_t)(bm + lrow1) * Dd + k0 + lcol1);
        cpa16(&Bs[st][lrow0 * 40 + lcol0], B + (size_t)(bn + lrow0) * Dd + k0 + lcol0);
        cpa16(&Bs[st][lrow1 * 40 + lcol1], B + (size_t)(bn + lrow1) * Dd + k0 + lcol1);
        cp_commit();
    }

#pragma unroll
    for (int ks = 0; ks < 8; ks++) {
        cp_wait1();
        __syncthreads();
        if (ks < 6) {
            int st = (ks + 2) % 3;
            int k0 = (ks + 2) * 32;
            cpa16(&As[st][lrow0 * 40 + lcol0], A + (size_t)(bm + lrow0) * Dd + k0 + lcol0);
            cpa16(&As[st][lrow1 * 40 + lcol1], A + (size_t)(bm + lrow1) * Dd + k0 + lcol1);
            cpa16(&Bs[st][lrow0 * 40 + lcol0], B + (size_t)(bn + lrow0) * Dd + k0 + lcol0);
            cpa16(&Bs[st][lrow1 * 40 + lcol1], B + (size_t)(bn + lrow1) * Dd + k0 + lcol1);
        }
        cp_commit();
        const __nv_bfloat16* as = As[ks % 3];
        const __nv_bfloat16* bs = Bs[ks % 3];
#pragma unroll
        for (int kk = 0; kk < 2; kk++) {
            int kb = kk * 16 + 2 * tig;
            unsigned af[4][4];
#pragma unroll
            for (int fm = 0; fm < 4; fm++) {
                int mrow = wm * 64 + fm * 16 + gid;
                af[fm][0] = *(const unsigned*)&as[mrow * 40 + kb];
                af[fm][1] = *(const unsigned*)&as[(mrow + 8) * 40 + kb];
                af[fm][2] = *(const unsigned*)&as[mrow * 40 + kb + 8];
                af[fm][3] = *(const unsigned*)&as[(mrow + 8) * 40 + kb + 8];
            }
            unsigned bfr[4][2];
#pragma unroll
            for (int fn = 0; fn < 4; fn++) {
                int nrow = wn * 32 + fn * 8 + gid;
                bfr[fn][0] = *(const unsigned*)&bs[nrow * 40 + kb];
                bfr[fn][1] = *(const unsigned*)&bs[nrow * 40 + kb + 8];
            }
#pragma unroll
            for (int fm = 0; fm < 4; fm++)
#pragma unroll
                for (int fn = 0; fn < 4; fn++)
                    mma16(acc[fm][fn], af[fm], bfr[fn]);
        }
    }

#pragma unroll
    for (int fn = 0; fn < 4; fn++) {
        int gc = bn + wn * 32 + fn * 8 + 2 * tig;
        float bv0 = bias[gc], bv1 = bias[gc + 1];
        float cs0 = 0.f, cs1 = 0.f, cq0 = 0.f, cq1 = 0.f;
#pragma unroll
        for (int fm = 0; fm < 4; fm++) {
            int gr = bm + wm * 64 + fm * 16 + gid;
            float2 o0 = make_float2(acc[fm][fn][0] + bv0, acc[fm][fn][1] + bv1);
            float2 o1 = make_float2(acc[fm][fn][2] + bv0, acc[fm][fn][3] + bv1);
            if (MODE == 1 || zsel == 0) {
                float* C = (MODE == 1) ? g_o : g_q;
                *(float2*)(C + (size_t)gr * Dd + gc) = o0;
                *(float2*)(C + (size_t)(gr + 8) * Dd + gc) = o1;
            } else {
                __nv_bfloat162* Ch = (__nv_bfloat162*)((zsel == 1) ? g_kh : g_vh);
                Ch[(size_t)gr * (Dd / 2) + (gc >> 1)] = __float22bfloat162_rn(o0);
                Ch[(size_t)(gr + 8) * (Dd / 2) + (gc >> 1)] = __float22bfloat162_rn(o1);
            }
            if (MODE == 1) {
                if (gr < Nn) {
                    cs0 += o0.x; cs1 += o0.y;
                    cq0 = fmaf(o0.x, o0.x, cq0); cq1 = fmaf(o0.y, o0.y, cq1);
                }
                if (gr + 8 < Nn) {
                    cs0 += o1.x; cs1 += o1.y;
                    cq0 = fmaf(o1.x, o1.x, cq0); cq1 = fmaf(o1.y, o1.y, cq1);
                }
            }
        }
        if (MODE == 1) {
#pragma unroll
            for (int o = 4; o <= 16; o <<= 1) {
                cs0 += __shfl_xor_sync(0xffffffffu, cs0, o);
                cs1 += __shfl_xor_sync(0xffffffffu, cs1, o);
                cq0 += __shfl_xor_sync(0xffffffffu, cq0, o);
                cq1 += __shfl_xor_sync(0xffffffffu, cq1, o);
            }
            if (gid == 0) {
                asm volatile("red.global.add.v2.f32 [%0], {%1,%2};"
                             :: "l"(&g_bnsum[gc]), "f"(cs0), "f"(cs1) : "memory");
                asm volatile("red.global.add.v2.f32 [%0], {%1,%2};"
                             :: "l"(&g_bnss[gc]), "f"(cq0), "f"(cq1) : "memory");
            }
        }
    }
}

// ---------------- bf16 helpers for aggregation ----------------
__device__ __forceinline__ float dot8(uint4 kx, float4 q0, float4 q1) {
    float2 p0 = __bfloat1622float2(*(__nv_bfloat162*)&kx.x);
    float2 p1 = __bfloat1622float2(*(__nv_bfloat162*)&kx.y);
    float2 p2 = __bfloat1622float2(*(__nv_bfloat162*)&kx.z);
    float2 p3 = __bfloat1622float2(*(__nv_bfloat162*)&kx.w);
    float d = p0.x * q0.x;
    d = fmaf(p0.y, q0.y, d);
    d = fmaf(p1.x, q0.z, d);
    d = fmaf(p1.y, q0.w, d);
    d = fmaf(p2.x, q1.x, d);
    d = fmaf(p2.y, q1.y, d);
    d = fmaf(p3.x, q1.z, d);
    d = fmaf(p3.y, q1.w, d);
    return d;
}

__device__ __forceinline__ void fma8(float4& a, float4& b, uint4 vx, float s) {
    float2 p0 = __bfloat1622float2(*(__nv_bfloat162*)&vx.x);
    float2 p1 = __bfloat1622float2(*(__nv_bfloat162*)&vx.y);
    float2 p2 = __bfloat1622float2(*(__nv_bfloat162*)&vx.z);
    float2 p3 = __bfloat1622float2(*(__nv_bfloat162*)&vx.w);
    a.x = fmaf(p0.x, s, a.x); a.y = fmaf(p0.y, s, a.y);
    a.z = fmaf(p1.x, s, a.z); a.w = fmaf(p1.y, s, a.w);
    b.x = fmaf(p2.x, s, b.x); b.y = fmaf(p2.y, s, b.y);
    b.z = fmaf(p3.x, s, b.z); b.w = fmaf(p3.y, s, b.w);
}

// ---------------- 5: CSR aggregation (+ zeroes BN accumulators for gemm1) ---------
__global__ void __launch_bounds__(256) k_agg() {
    int tid = threadIdx.x;
    if (blockIdx.x == 0) {           // re-zero BN stats before gemm1's REDs
        g_bnsum[tid] = 0.0f;
        g_bnss[tid] = 0.0f;
    }
    int lane = tid & 31;
    int w = tid >> 5;
    int n = blockIdx.x * 8 + w;
    int grp0 = lane & ~7;

    const float4* qr = (const float4*)(g_q + (size_t)n * Dd);
    float4 q0 = qr[lane * 2], q1 = qr[lane * 2 + 1];
    float4 accA = make_float4(0.f, 0.f, 0.f, 0.f);
    float4 accB = make_float4(0.f, 0.f, 0.f, 0.f);
    float z = 0.0f;
    int e = g_off[n];
    const int end = g_off[n + 1];
    const char* kbase = (const char*)g_kh;
    const char* vbase = (const char*)g_vh;
    const size_t loff = (size_t)lane * 16;

    int pn0 = 0, pn1 = 0, pn2 = 0, pn3 = 0;
    if (e + 4 <= end) {
        pn0 = g_csrc[e]; pn1 = g_csrc[e + 1];
        pn2 = g_csrc[e + 2]; pn3 = g_csrc[e + 3];
    }
    for (; e + 4 <= end; ) {
        int s0 = pn0, s1 = pn1, s2 = pn2, s3 = pn3;
        int e2 = e + 4;
        uint4 k0 = *(const uint4*)(kbase + (size_t)s0 * 512 + loff);
        uint4 k1 = *(const uint4*)(kbase + (size_t)s1 * 512 + loff);
        uint4 k2 = *(const uint4*)(kbase + (size_t)s2 * 512 + loff);
        uint4 k3 = *(const uint4*)(kbase + (size_t)s3 * 512 + loff);
        uint4 v0 = *(const uint4*)(vbase + (size_t)s0 * 512 + loff);
        uint4 v1 = *(const uint4*)(vbase + (size_t)s1 * 512 + loff);
        uint4 v2 = *(const uint4*)(vbase + (size_t)s2 * 512 + loff);
        uint4 v3 = *(const uint4*)(vbase + (size_t)s3 * 512 + loff);
        if (e2 + 4 <= end) {
            pn0 = g_csrc[e2]; pn1 = g_csrc[e2 + 1];
            pn2 = g_csrc[e2 + 2]; pn3 = g_csrc[e2 + 3];
        }
        float d0 = dot8(k0, q0, q1);
        float d1 = dot8(k1, q0, q1);
        float d2 = dot8(k2, q0, q1);
        float d3 = dot8(k3, q0, q1);
        d0 += __shfl_down_sync(0xffffffffu, d0, 4, 8);
        d1 += __shfl_down_sync(0xffffffffu, d1, 4, 8);
        d2 += __shfl_down_sync(0xffffffffu, d2, 4, 8);
        d3 += __shfl_down_sync(0xffffffffu, d3, 4, 8);
        d0 += __shfl_down_sync(0xffffffffu, d0, 2, 8);
        d1 += __shfl_down_sync(0xffffffffu, d1, 2, 8);
        d2 += __shfl_down_sync(0xffffffffu, d2, 2, 8);
        d3 += __shfl_down_sync(0xffffffffu, d3, 2, 8);
        d0 += __shfl_down_sync(0xffffffffu, d0, 1, 8);
        d1 += __shfl_down_sync(0xffffffffu, d1, 1, 8);
        d2 += __shfl_down_sync(0xffffffffu, d2, 1, 8);
        d3 += __shfl_down_sync(0xffffffffu, d3, 1, 8);
        d0 = __shfl_sync(0xffffffffu, d0, grp0);
        d1 = __shfl_sync(0xffffffffu, d1, grp0);
        d2 = __shfl_sync(0xffffffffu, d2, grp0);
        d3 = __shfl_sync(0xffffffffu, d3, grp0);
        float sv0 = __expf(fminf(fmaxf(d0 * 0.125f, -5.0f), 5.0f));
        float sv1 = __expf(fminf(fmaxf(d1 * 0.125f, -5.0f), 5.0f));
        float sv2 = __expf(fminf(fmaxf(d2 * 0.125f, -5.0f), 5.0f));
        float sv3 = __expf(fminf(fmaxf(d3 * 0.125f, -5.0f), 5.0f));
        z += (sv0 + sv1) + (sv2 + sv3);
        fma8(accA, accB, v0, sv0);
        fma8(accA, accB, v1, sv1);
        fma8(accA, accB, v2, sv2);
        fma8(accA, accB, v3, sv3);
        e = e2;
    }
    for (; e < end; e++) {
        int s0 = g_csrc[e];
        uint4 k0 = *(const uint4*)(kbase + (size_t)s0 * 512 + loff);
        uint4 v0 = *(const uint4*)(vbase + (size_t)s0 * 512 + loff);
        float d0 = dot8(k0, q0, q1);
        d0 += __shfl_down_sync(0xffffffffu, d0, 4, 8);
        d0 += __shfl_down_sync(0xffffffffu, d0, 2, 8);
        d0 += __shfl_down_sync(0xffffffffu, d0, 1, 8);
        d0 = __shfl_sync(0xffffffffu, d0, grp0);
        float sv0 = __expf(fminf(fmaxf(d0 * 0.125f, -5.0f), 5.0f));
        z += sv0;
        fma8(accA, accB, v0, sv0);
    }
    float inv = 1.0f / z;
    uint4 pk;
    __nv_bfloat162 b0 = __float22bfloat162_rn(make_float2(accA.x * inv, accA.y * inv));
    __nv_bfloat162 b1 = __float22bfloat162_rn(make_float2(accA.z * inv, accA.w * inv));
    __nv_bfloat162 b2 = __float22bfloat162_rn(make_float2(accB.x * inv, accB.y * inv));
    __nv_bfloat162 b3 = __float22bfloat162_rn(make_float2(accB.z * inv, accB.w * inv));
    pk.x = *(unsigned*)&b0; pk.y = *(unsigned*)&b1;
    pk.z = *(unsigned*)&b2; pk.w = *(unsigned*)&b3;
    *(uint4*)((char*)g_wv + (size_t)n * 512 + loff) = pk;
}

// ---------------- 7: fused BN + ReLU6 + SE + hardswish + residual + counter reset --
__global__ void __launch_bounds__(256) k_se(const float* __restrict__ gamma,
                                            const float* __restrict__ beta,
                                            const float* __restrict__ W1,
                                            const float* __restrict__ b1,
                                            const float* __restrict__ W2,
                                            const float* __restrict__ b2,
                                            const float* __restrict__ v,
                                            float* __restrict__ out) {
    __shared__ float xs[16][256];
    __shared__ float hs[16][64];
    __shared__ float sa[256], sb[256];
    int t = threadIdx.x;
    int row0 = blockIdx.x * 16;

    // reset counters for next graph replay (each block owns its 16 nodes)
    if (t < 16) {
        g_cin[row0 + t] = 0;
        g_cout[row0 + t] = 0;
    }
    if (blockIdx.x == 0 && t == 0) {
        g_flag = 0;
        g_maxdeg = 0;
        g_sumexp = 0.0f;
    }

    {
        float mean = g_bnsum[t] * (1.0f / Nn);
        float var = g_bnss[t] * (1.0f / Nn) - mean * mean;
        float istd = rsqrtf(var + BN_EPS);
        float a = gamma[t] * istd;
        sa[t] = a;
        sb[t] = beta[t] - mean * a;
    }
    __syncthreads();

    for (int i = t; i < 16 * 256; i += 256) {
        int r = i >> 8, c = i & 255;
        float xv = fmaf(sa[c], g_o[(size_t)(row0 + r) * Dd + c], sb[c]);
        xs[r][c] = fminf(fmaxf(xv, 0.0f), 6.0f);
    }
    __syncthreads();

    {
        int hc = t & 63, rg = t >> 6;
        float acc0 = b1[hc], acc1 = acc0, acc2 = acc0, acc3 = acc0;
        for (int k = 0; k < 256; k++) {
            float w = W1[k * 64 + hc];
            acc0 = fmaf(xs[rg * 4 + 0][k], w, acc0);
            acc1 = fmaf(xs[rg * 4 + 1][k], w, acc1);
            acc2 = fmaf(xs[rg * 4 + 2][k], w, acc2);
            acc3 = fmaf(xs[rg * 4 + 3][k], w, acc3);
        }
        hs[rg * 4 + 0][hc] = fminf(fmaxf(acc0, 0.0f), 6.0f);
        hs[rg * 4 + 1][hc] = fminf(fmaxf(acc1, 0.0f), 6.0f);
        hs[rg * 4 + 2][hc] = fminf(fmaxf(acc2, 0.0f), 6.0f);
        hs[rg * 4 + 3][hc] = fminf(fmaxf(acc3, 0.0f), 6.0f);
    }
    __syncthreads();

    {
        int col = t;
        float acc[16];
        float bb = b2[col];
#pragma unroll
        for (int r = 0; r < 16; r++) acc[r] = bb;
        for (int k = 0; k < 64; k++) {
            float w = W2[k * 256 + col];
#pragma unroll
            for (int r = 0; r < 16; r++) acc[r] = fmaf(hs[r][k], w, acc[r]);
        }
#pragma unroll
        for (int r = 0; r < 16; r++) {
            float u = acc[r];
            float act = u * __saturatef((u + 3.0f) * (1.0f / 6.0f));
            size_t idx = (size_t)(row0 + r) * Dd + col;
            out[idx] = fmaf(act, xs[r][col], v[idx]);
        }
    }
}

// ---------------- launch ----------------
extern "C" void kernel_launch(void* const* d_in, const int* in_sizes, int n_in,
                              void* d_out, int out_size) {
    const float* v     = (const float*)d_in[0];
    const float* WQ    = (const float*)d_in[1];
    const float* bQ    = (const float*)d_in[2];
    const float* WK    = (const float*)d_in[3];
    const float* bK    = (const float*)d_in[4];
    const float* WV    = (const float*)d_in[5];
    const float* bV    = (const float*)d_in[6];
    const float* Wo    = (const float*)d_in[7];
    const float* bo    = (const float*)d_in[8];
    const float* W1    = (const float*)d_in[9];
    const float* b1    = (const float*)d_in[10];
    const float* W2    = (const float*)d_in[11];
    const float* b2    = (const float*)d_in[12];
    const float* gamma = (const float*)d_in[13];
    const float* beta  = (const float*)d_in[14];
    const int*   src   = (const int*)d_in[15];
    const int*   dst   = (const int*)d_in[16];
    float* out = (float*)d_out;

    cudaStream_t s2 = g_ss.s2;

    k_scan<<<SCANB, 256>>>(src, dst);
    cudaEventRecord(g_ss.ev_scan, 0);

    // side stream: scatter (only consumer is k_agg) — overlaps prep + QKV GEMM
    cudaStreamWaitEvent(s2, g_ss.ev_scan, 0);
    k_scatter<<<(Ee + 255) / 256, 256, 0, s2>>>(src, dst);
    cudaEventRecord(g_ss.ev_s2, s2);

    // main stream continues
    k_prep<<<256 + (Nn * Dd / 4 + 255) / 256, 256>>>(v, WQ, WK, WV, Wo);
    k_gemm_bf16<0><<<dim3(2, 79, 3), 256>>>(bQ, bK, bV);

    cudaStreamWaitEvent(0, g_ss.ev_s2, 0);
    k_agg<<<1250, 256>>>();

    k_gemm_bf16<1><<<dim3(2, 79, 1), 256>>>(bo, nullptr, nullptr);

    k_se<<<Nn / 16, 256>>>(gamma, beta, W1, b1, W2, b2, v, out);
}

// round 16
// speedup vs baseline: 1.0565x; 1.0565x over previous
#include <cuda_runtime.h>
#include <cuda_bf16.h>
#include <math.h>

#define Nn 10000
#define Ee 320000
#define Dd 256
#define Hh 4
#define BN_EPS 1e-5f
#define MROWS 10112   // 79 * 128 padded rows
#define SCANB 40      // scan blocks (40*256 >= Nn)

// ---------------- scratch (device globals) ----------------
__device__ int   g_cin[Nn];
__device__ int   g_cout[Nn];
__device__ int   g_off[Nn + 1];
__device__ int   g_fill[Nn];
__device__ int   g_csrc[Ee];
__device__ int   g_bsum[SCANB];
__device__ int   g_flag;
__device__ int   g_maxdeg;
__device__ float g_sumexp;
__device__ float g_ex[Nn];
__device__ __nv_bfloat16 g_mVh[MROWS * Dd];  // bf16 center-scaled mV (row-major)
__device__ float g_q[MROWS * Dd];            // fp32 q
__device__ __nv_bfloat16 g_kh[MROWS * Dd];   // bf16 k
__device__ __nv_bfloat16 g_vh[MROWS * Dd];   // bf16 vv
__device__ __nv_bfloat16 g_wv[MROWS * Dd];   // bf16 normalized wv (row-major)
__device__ float g_o[MROWS * Dd];
__device__ __nv_bfloat16 g_Wth[4 * Dd * Dd]; // bf16 transposed weights [z][n][k]
__device__ float g_bnsum[Dd];
__device__ float g_bnss[Dd];

// ---------------- side stream + events (created at load) ----------------
struct SideStream {
    cudaStream_t s2;
    cudaEvent_t ev_scan, ev_s2;
    SideStream() {
        cudaStreamCreateWithFlags(&s2, cudaStreamNonBlocking);
        cudaEventCreateWithFlags(&ev_scan, cudaEventDisableTiming);
        cudaEventCreateWithFlags(&ev_s2, cudaEventDisableTiming);
    }
};
static SideStream g_ss;

// ---------------- 0: zero scratch ----------------
__global__ void k_zero() {
    int i = blockIdx.x * blockDim.x + threadIdx.x;
    if (i < Nn) { g_cin[i] = 0; g_cout[i] = 0; }
    if (i < Dd) { g_bnsum[i] = 0.0f; g_bnss[i] = 0.0f; }
    if (i == 0) { g_maxdeg = 0; g_sumexp = 0.0f; g_flag = 0; }
}

// ---------------- 1: in/out degree histograms ----------------
__global__ void k_count(const int* __restrict__ src, const int* __restrict__ dst) {
    int e = blockIdx.x * blockDim.x + threadIdx.x;
    if (e < Ee) {
        atomicAdd(&g_cout[src[e]], 1);
        atomicAdd(&g_cin[dst[e]], 1);
    }
}

// ---------------- 1b: fused scan + softmax prep (single kernel, flag-based sync) ---
__global__ void __launch_bounds__(256) k_scan() {
    __shared__ int wsum[8];
    __shared__ int wmax[8];
    __shared__ float wred[8];
    __shared__ int pre_s;
    int t = threadIdx.x;
    int lane = t & 31, w = t >> 5;
    int bid = blockIdx.x;
    int n = bid * 256 + t;
    int ci = (n < Nn) ? g_cin[n] : 0;
    int co = (n < Nn) ? g_cout[n] : 0;
    int deg = ci + co;

    int x = ci;
#pragma unroll
    for (int o = 1; o < 32; o <<= 1) {
        int y = __shfl_up_sync(0xffffffffu, x, o);
        if (lane >= o) x += y;
    }
    int m = deg;
#pragma unroll
    for (int o = 16; o > 0; o >>= 1) m = max(m, __shfl_xor_sync(0xffffffffu, m, o));

    if (lane == 31) wsum[w] = x;
    if (lane == 0) wmax[w] = m;
    __syncthreads();
    if (w == 0) {
        int v = (lane < 8) ? wsum[lane] : 0;
#pragma unroll
        for (int o = 1; o < 8; o <<= 1) {
            int y = __shfl_up_sync(0xffffffffu, v, o);
            if (lane >= o) v += y;
        }
        if (lane < 8) wsum[lane] = v;
        int mm = (lane < 8) ? wmax[lane] : 0;
#pragma unroll
        for (int o = 4; o > 0; o >>= 1) mm = max(mm, __shfl_xor_sync(0xffffffffu, mm, o));
        if (lane == 0) {
            atomicMax(&g_maxdeg, mm);
            g_bsum[bid] = wsum[7];
            __threadfence();
            atomicAdd(&g_flag, 1);
        }
    }
    if (t == 0) {
        while (atomicAdd(&g_flag, 0) < SCANB) { }
    }
    __syncthreads();

    if (t < 32) {
        int v = (t < bid) ? g_bsum[t] : 0;
        if (t + 32 < bid) v += g_bsum[t + 32];
#pragma unroll
        for (int o = 16; o > 0; o >>= 1) v += __shfl_xor_sync(0xffffffffu, v, o);
        if (t == 0) pre_s = v;
    }
    __syncthreads();

    int wpre = (w > 0) ? wsum[w - 1] : 0;
    int off = pre_s + wpre + x - ci;
    int maxdeg = g_maxdeg;
    float ex = 0.0f;
    if (n < Nn) {
        g_off[n] = off;
        g_fill[n] = off;
        ex = expf((float)(deg - maxdeg));
        g_ex[n] = ex;
    }
    if (bid == 0 && t == 0) g_off[Nn] = Ee;

    float s = ex;
#pragma unroll
    for (int o = 16; o > 0; o >>= 1) s += __shfl_xor_sync(0xffffffffu, s, o);
    if (lane == 0) wred[w] = s;
    __syncthreads();
    if (w == 0) {
        float v = (lane < 8) ? wred[lane] : 0.0f;
#pragma unroll
        for (int o = 4; o > 0; o >>= 1) v += __shfl_xor_sync(0xffffffffu, v, o);
        if (lane == 0) atomicAdd(&g_sumexp, v);
    }
}

// ---------------- 1c: scatter src ids into CSR order ----------------
__global__ void k_scatter(const int* __restrict__ src, const int* __restrict__ dst) {
    int e = blockIdx.x * blockDim.x + threadIdx.x;
    if (e < Ee) {
        int d = dst[e];
        int pos = atomicAdd(&g_fill[d], 1);
        g_csrc[pos] = src[e];
    }
}

// ---------------- 2: fused prep — weight transpose (blocks 0..255) + mv (rest) -----
__global__ void __launch_bounds__(256) k_prep(const float* __restrict__ v,
                                              const float* __restrict__ WQ,
                                              const float* __restrict__ WK,
                                              const float* __restrict__ WV,
                                              const float* __restrict__ Wo) {
    int b = blockIdx.x;
    if (b < 256) {
        __shared__ float tl[32][33];
        int z = b >> 6;
        int idx = b & 63;
        int k0 = (idx & 7) * 32, n0 = (idx >> 3) * 32;
        const float* W = (z == 0) ? WQ : (z == 1) ? WK : (z == 2) ? WV : Wo;
        int tx = threadIdx.x & 31, ty = threadIdx.x >> 5;
#pragma unroll
        for (int j = 0; j < 32; j += 8)
            tl[ty + j][tx] = W[(size_t)(k0 + ty + j) * Dd + n0 + tx];
        __syncthreads();
#pragma unroll
        for (int j = 0; j < 32; j += 8)
            g_Wth[(size_t)z * Dd * Dd + (size_t)(n0 + ty + j) * Dd + k0 + tx] =
                __float2bfloat16(tl[tx][ty + j]);
    } else {
        int i4 = (b - 256) * 256 + threadIdx.x;
        if (i4 >= Nn * Dd / 4) return;
        int n = i4 >> 6;
        float c = g_ex[n] / g_sumexp;
        float4 a = ((const float4*)v)[i4];
        __nv_bfloat162 p0 = __float22bfloat162_rn(make_float2(a.x * c, a.y * c));
        __nv_bfloat162 p1 = __float22bfloat162_rn(make_float2(a.z * c, a.w * c));
        __nv_bfloat162* o = (__nv_bfloat162*)g_mVh;
        o[i4 * 2]     = p0;
        o[i4 * 2 + 1] = p1;
    }
}

// ---------------- cp.async helpers ----------------
__device__ __forceinline__ void cpa16(void* s, const void* g) {
    unsigned sa = (unsigned)__cvta_generic_to_shared(s);
    asm volatile("cp.async.ca.shared.global [%0], [%1], 16;" :: "r"(sa), "l"(g));
}
__device__ __forceinline__ void cp_commit() { asm volatile("cp.async.commit_group;"); }
__device__ __forceinline__ void cp_wait1() { asm volatile("cp.async.wait_group 1;"); }

__device__ __forceinline__ void mma16(float* c, const unsigned* a, const unsigned* b) {
    asm volatile(
        "mma.sync.aligned.m16n8k16.row.col.f32.bf16.bf16.f32 "
        "{%0,%1,%2,%3},{%4,%5,%6,%7},{%8,%9},{%0,%1,%2,%3};"
        : "+f"(c[0]), "+f"(c[1]), "+f"(c[2]), "+f"(c[3])
        : "r"(a[0]), "r"(a[1]), "r"(a[2]), "r"(a[3]), "r"(b[0]), "r"(b[1]));
}

// ---------------- 4: bf16 tensor-core GEMM, 3-stage cp.async, 2 CTAs/SM -----------
// __launch_bounds__(256, 2): R15 profile showed regs=142 -> 1 CTA/SM, occ 12.5%,
// tensor pipe 23.7%. Capping regs to fit 2 CTAs doubles latency hiding.
template <int MODE>
__global__ void __launch_bounds__(256, 2) k_gemm_bf16(
    const float* __restrict__ ba, const float* __restrict__ bb, const float* __restrict__ bc) {
    __shared__ __nv_bfloat16 As[3][128 * 40];
    __shared__ __nv_bfloat16 Bs[3][128 * 40];

    const int zsel = (MODE == 0) ? blockIdx.z : 3;
    const __nv_bfloat16* A = (MODE == 0) ? g_mVh : g_wv;
    const __nv_bfloat16* B = g_Wth + (size_t)zsel * Dd * Dd;
    const float* bias = (MODE == 1) ? ba : (zsel == 0) ? ba : (zsel == 1) ? bb : bc;

    const int tid = threadIdx.x;
    const int lane = tid & 31;
    const int warp = tid >> 5;
    const int wm = warp & 1;
    const int wn = warp >> 1;
    const int gid = lane >> 2;
    const int tig = lane & 3;
    const int bm = blockIdx.y * 128;
    const int bn = blockIdx.x * 128;

    const int lrow0 = tid >> 2;
    const int lcol0 = (tid & 3) * 8;
    const int lrow1 = (tid + 256) >> 2;
    const int lcol1 = lcol0;

    float acc[4][4][4];
#pragma unroll
    for (int i = 0; i < 4; i++)
#pragma unroll
        for (int j = 0; j < 4; j++)
#pragma unroll
            for (int q = 0; q < 4; q++) acc[i][j][q] = 0.0f;

#pragma unroll
    for (int st = 0; st < 2; st++) {
        int k0 = st * 32;
        cpa16(&As[st][lrow0 * 40 + lcol0], A + (size_t)(bm + lrow0) * Dd + k0 + lcol0);
        cpa16(&As[st][lrow1 * 40 + lcol1], A + (size_t)(bm + lrow1) * Dd + k0 + lcol1);
        cpa16(&Bs[st][lrow0 * 40 + lcol0], B + (size_t)(bn + lrow0) * Dd + k0 + lcol0);
        cpa16(&Bs[st][lrow1 * 40 + lcol1], B + (size_t)(bn + lrow1) * Dd + k0 + lcol1);
        cp_commit();
    }

#pragma unroll
    for (int ks = 0; ks < 8; ks++) {
        cp_wait1();
        __syncthreads();
        if (ks < 6) {
            int st = (ks + 2) % 3;
            int k0 = (ks + 2) * 32;
            cpa16(&As[st][lrow0 * 40 + lcol0], A + (size_t)(bm + lrow0) * Dd + k0 + lcol0);
            cpa16(&As[st][lrow1 * 40 + lcol1], A + (size_t)(bm + lrow1) * Dd + k0 + lcol1);
            cpa16(&Bs[st][lrow0 * 40 + lcol0], B + (size_t)(bn + lrow0) * Dd + k0 + lcol0);
            cpa16(&Bs[st][lrow1 * 40 + lcol1], B + (size_t)(bn + lrow1) * Dd + k0 + lcol1);
        }
        cp_commit();
        const __nv_bfloat16* as = As[ks % 3];
        const __nv_bfloat16* bs = Bs[ks % 3];
#pragma unroll
        for (int kk = 0; kk < 2; kk++) {
            int kb = kk * 16 + 2 * tig;
            unsigned af[4][4];
#pragma unroll
            for (int fm = 0; fm < 4; fm++) {
                int mrow = wm * 64 + fm * 16 + gid;
                af[fm][0] = *(const unsigned*)&as[mrow * 40 + kb];
                af[fm][1] = *(const unsigned*)&as[(mrow + 8) * 40 + kb];
                af[fm][2] = *(const unsigned*)&as[mrow * 40 + kb + 8];
                af[fm][3] = *(const unsigned*)&as[(mrow + 8) * 40 + kb + 8];
            }
            unsigned bfr[4][2];
#pragma unroll
            for (int fn = 0; fn < 4; fn++) {
                int nrow = wn * 32 + fn * 8 + gid;
                bfr[fn][0] = *(const unsigned*)&bs[nrow * 40 + kb];
                bfr[fn][1] = *(const unsigned*)&bs[nrow * 40 + kb + 8];
            }
#pragma unroll
            for (int fm = 0; fm < 4; fm++)
#pragma unroll
                for (int fn = 0; fn < 4; fn++)
                    mma16(acc[fm][fn], af[fm], bfr[fn]);
        }
    }

#pragma unroll
    for (int fn = 0; fn < 4; fn++) {
        int gc = bn + wn * 32 + fn * 8 + 2 * tig;
        float bv0 = bias[gc], bv1 = bias[gc + 1];
        float cs0 = 0.f, cs1 = 0.f, cq0 = 0.f, cq1 = 0.f;
#pragma unroll
        for (int fm = 0; fm < 4; fm++) {
            int gr = bm + wm * 64 + fm * 16 + gid;
            float2 o0 = make_float2(acc[fm][fn][0] + bv0, acc[fm][fn][1] + bv1);
            float2 o1 = make_float2(acc[fm][fn][2] + bv0, acc[fm][fn][3] + bv1);
            if (MODE == 1 || zsel == 0) {
                float* C = (MODE == 1) ? g_o : g_q;
                *(float2*)(C + (size_t)gr * Dd + gc) = o0;
                *(float2*)(C + (size_t)(gr + 8) * Dd + gc) = o1;
            } else {
                __nv_bfloat162* Ch = (__nv_bfloat162*)((zsel == 1) ? g_kh : g_vh);
                Ch[(size_t)gr * (Dd / 2) + (gc >> 1)] = __float22bfloat162_rn(o0);
                Ch[(size_t)(gr + 8) * (Dd / 2) + (gc >> 1)] = __float22bfloat162_rn(o1);
            }
            if (MODE == 1) {
                if (gr < Nn) {
                    cs0 += o0.x; cs1 += o0.y;
                    cq0 = fmaf(o0.x, o0.x, cq0); cq1 = fmaf(o0.y, o0.y, cq1);
                }
                if (gr + 8 < Nn) {
                    cs0 += o1.x; cs1 += o1.y;
                    cq0 = fmaf(o1.x, o1.x, cq0); cq1 = fmaf(o1.y, o1.y, cq1);
                }
            }
        }
        if (MODE == 1) {
#pragma unroll
            for (int o = 4; o <= 16; o <<= 1) {
                cs0 += __shfl_xor_sync(0xffffffffu, cs0, o);
                cs1 += __shfl_xor_sync(0xffffffffu, cs1, o);
                cq0 += __shfl_xor_sync(0xffffffffu, cq0, o);
                cq1 += __shfl_xor_sync(0xffffffffu, cq1, o);
            }
            if (gid == 0) {
                asm volatile("red.global.add.v2.f32 [%0], {%1,%2};"
                             :: "l"(&g_bnsum[gc]), "f"(cs0), "f"(cs1) : "memory");
                asm volatile("red.global.add.v2.f32 [%0], {%1,%2};"
                             :: "l"(&g_bnss[gc]), "f"(cq0), "f"(cq1) : "memory");
            }
        }
    }
}

// ---------------- bf16 helpers for aggregation ----------------
__device__ __forceinline__ float dot8(uint4 kx, float4 q0, float4 q1) {
    float2 p0 = __bfloat1622float2(*(__nv_bfloat162*)&kx.x);
    float2 p1 = __bfloat1622float2(*(__nv_bfloat162*)&kx.y);
    float2 p2 = __bfloat1622float2(*(__nv_bfloat162*)&kx.z);
    float2 p3 = __bfloat1622float2(*(__nv_bfloat162*)&kx.w);
    float d = p0.x * q0.x;
    d = fmaf(p0.y, q0.y, d);
    d = fmaf(p1.x, q0.z, d);
    d = fmaf(p1.y, q0.w, d);
    d = fmaf(p2.x, q1.x, d);
    d = fmaf(p2.y, q1.y, d);
    d = fmaf(p3.x, q1.z, d);
    d = fmaf(p3.y, q1.w, d);
    return d;
}

__device__ __forceinline__ void fma8(float4& a, float4& b, uint4 vx, float s) {
    float2 p0 = __bfloat1622float2(*(__nv_bfloat162*)&vx.x);
    float2 p1 = __bfloat1622float2(*(__nv_bfloat162*)&vx.y);
    float2 p2 = __bfloat1622float2(*(__nv_bfloat162*)&vx.z);
    float2 p3 = __bfloat1622float2(*(__nv_bfloat162*)&vx.w);
    a.x = fmaf(p0.x, s, a.x); a.y = fmaf(p0.y, s, a.y);
    a.z = fmaf(p1.x, s, a.z); a.w = fmaf(p1.y, s, a.w);
    b.x = fmaf(p2.x, s, b.x); b.y = fmaf(p2.y, s, b.y);
    b.z = fmaf(p3.x, s, b.z); b.w = fmaf(p3.y, s, b.w);
}

// ---------------- 5: CSR aggregation: one warp per node, pipelined index loads ----
__global__ void __launch_bounds__(256) k_agg() {
    int tid = threadIdx.x;
    int lane = tid & 31;
    int w = tid >> 5;
    int n = blockIdx.x * 8 + w;
    int grp0 = lane & ~7;

    const float4* qr = (const float4*)(g_q + (size_t)n * Dd);
    float4 q0 = qr[lane * 2], q1 = qr[lane * 2 + 1];
    float4 accA = make_float4(0.f, 0.f, 0.f, 0.f);
    float4 accB = make_float4(0.f, 0.f, 0.f, 0.f);
    float z = 0.0f;
    int e = g_off[n];
    const int end = g_off[n + 1];
    const char* kbase = (const char*)g_kh;
    const char* vbase = (const char*)g_vh;
    const size_t loff = (size_t)lane * 16;

    int pn0 = 0, pn1 = 0, pn2 = 0, pn3 = 0;
    if (e + 4 <= end) {
        pn0 = g_csrc[e]; pn1 = g_csrc[e + 1];
        pn2 = g_csrc[e + 2]; pn3 = g_csrc[e + 3];
    }
    for (; e + 4 <= end; ) {
        int s0 = pn0, s1 = pn1, s2 = pn2, s3 = pn3;
        int e2 = e + 4;
        uint4 k0 = *(const uint4*)(kbase + (size_t)s0 * 512 + loff);
        uint4 k1 = *(const uint4*)(kbase + (size_t)s1 * 512 + loff);
        uint4 k2 = *(const uint4*)(kbase + (size_t)s2 * 512 + loff);
        uint4 k3 = *(const uint4*)(kbase + (size_t)s3 * 512 + loff);
        uint4 v0 = *(const uint4*)(vbase + (size_t)s0 * 512 + loff);
        uint4 v1 = *(const uint4*)(vbase + (size_t)s1 * 512 + loff);
        uint4 v2 = *(const uint4*)(vbase + (size_t)s2 * 512 + loff);
        uint4 v3 = *(const uint4*)(vbase + (size_t)s3 * 512 + loff);
        if (e2 + 4 <= end) {
            pn0 = g_csrc[e2]; pn1 = g_csrc[e2 + 1];
            pn2 = g_csrc[e2 + 2]; pn3 = g_csrc[e2 + 3];
        }
        float d0 = dot8(k0, q0, q1);
        float d1 = dot8(k1, q0, q1);
        float d2 = dot8(k2, q0, q1);
        float d3 = dot8(k3, q0, q1);
        d0 += __shfl_down_sync(0xffffffffu, d0, 4, 8);
        d1 += __shfl_down_sync(0xffffffffu, d1, 4, 8);
        d2 += __shfl_down_sync(0xffffffffu, d2, 4, 8);
        d3 += __shfl_down_sync(0xffffffffu, d3, 4, 8);
        d0 += __shfl_down_sync(0xffffffffu, d0, 2, 8);
        d1 += __shfl_down_sync(0xffffffffu, d1, 2, 8);
        d2 += __shfl_down_sync(0xffffffffu, d2, 2, 8);
        d3 += __shfl_down_sync(0xffffffffu, d3, 2, 8);
        d0 += __shfl_down_sync(0xffffffffu, d0, 1, 8);
        d1 += __shfl_down_sync(0xffffffffu, d1, 1, 8);
        d2 += __shfl_down_sync(0xffffffffu, d2, 1, 8);
        d3 += __shfl_down_sync(0xffffffffu, d3, 1, 8);
        d0 = __shfl_sync(0xffffffffu, d0, grp0);
        d1 = __shfl_sync(0xffffffffu, d1, grp0);
        d2 = __shfl_sync(0xffffffffu, d2, grp0);
        d3 = __shfl_sync(0xffffffffu, d3, grp0);
        float sv0 = __expf(fminf(fmaxf(d0 * 0.125f, -5.0f), 5.0f));
        float sv1 = __expf(fminf(fmaxf(d1 * 0.125f, -5.0f), 5.0f));
        float sv2 = __expf(fminf(fmaxf(d2 * 0.125f, -5.0f), 5.0f));
        float sv3 = __expf(fminf(fmaxf(d3 * 0.125f, -5.0f), 5.0f));
        z += (sv0 + sv1) + (sv2 + sv3);
        fma8(accA, accB, v0, sv0);
        fma8(accA, accB, v1, sv1);
        fma8(accA, accB, v2, sv2);
        fma8(accA, accB, v3, sv3);
        e = e2;
    }
    for (; e < end; e++) {
        int s0 = g_csrc[e];
        uint4 k0 = *(const uint4*)(kbase + (size_t)s0 * 512 + loff);
        uint4 v0 = *(const uint4*)(vbase + (size_t)s0 * 512 + loff);
        float d0 = dot8(k0, q0, q1);
        d0 += __shfl_down_sync(0xffffffffu, d0, 4, 8);
        d0 += __shfl_down_sync(0xffffffffu, d0, 2, 8);
        d0 += __shfl_down_sync(0xffffffffu, d0, 1, 8);
        d0 = __shfl_sync(0xffffffffu, d0, grp0);
        float sv0 = __expf(fminf(fmaxf(d0 * 0.125f, -5.0f), 5.0f));
        z += sv0;
        fma8(accA, accB, v0, sv0);
    }
    float inv = 1.0f / z;
    uint4 pk;
    __nv_bfloat162 b0 = __float22bfloat162_rn(make_float2(accA.x * inv, accA.y * inv));
    __nv_bfloat162 b1 = __float22bfloat162_rn(make_float2(accA.z * inv, accA.w * inv));
    __nv_bfloat162 b2 = __float22bfloat162_rn(make_float2(accB.x * inv, accB.y * inv));
    __nv_bfloat162 b3 = __float22bfloat162_rn(make_float2(accB.z * inv, accB.w * inv));
    pk.x = *(unsigned*)&b0; pk.y = *(unsigned*)&b1;
    pk.z = *(unsigned*)&b2; pk.w = *(unsigned*)&b3;
    *(uint4*)((char*)g_wv + (size_t)n * 512 + loff) = pk;
}

// ---------------- 7: fused BN + ReLU6 + SE + hardswish + residual ----------------
__global__ void __launch_bounds__(256) k_se(const float* __restrict__ gamma,
                                            const float* __restrict__ beta,
                                            const float* __restrict__ W1,
                                            const float* __restrict__ b1,
                                            const float* __restrict__ W2,
                                            const float* __restrict__ b2,
                                            const float* __restrict__ v,
                                            float* __restrict__ out) {
    __shared__ float xs[16][256];
    __shared__ float hs[16][64];
    __shared__ float sa[256], sb[256];
    int t = threadIdx.x;
    int row0 = blockIdx.x * 16;

    {
        float mean = g_bnsum[t] * (1.0f / Nn);
        float var = g_bnss[t] * (1.0f / Nn) - mean * mean;
        float istd = rsqrtf(var + BN_EPS);
        float a = gamma[t] * istd;
        sa[t] = a;
        sb[t] = beta[t] - mean * a;
    }
    __syncthreads();

    for (int i = t; i < 16 * 256; i += 256) {
        int r = i >> 8, c = i & 255;
        float xv = fmaf(sa[c], g_o[(size_t)(row0 + r) * Dd + c], sb[c]);
        xs[r][c] = fminf(fmaxf(xv, 0.0f), 6.0f);
    }
    __syncthreads();

    {
        int hc = t & 63, rg = t >> 6;
        float acc0 = b1[hc], acc1 = acc0, acc2 = acc0, acc3 = acc0;
        for (int k = 0; k < 256; k++) {
            float w = W1[k * 64 + hc];
            acc0 = fmaf(xs[rg * 4 + 0][k], w, acc0);
            acc1 = fmaf(xs[rg * 4 + 1][k], w, acc1);
            acc2 = fmaf(xs[rg * 4 + 2][k], w, acc2);
            acc3 = fmaf(xs[rg * 4 + 3][k], w, acc3);
        }
        hs[rg * 4 + 0][hc] = fminf(fmaxf(acc0, 0.0f), 6.0f);
        hs[rg * 4 + 1][hc] = fminf(fmaxf(acc1, 0.0f), 6.0f);
        hs[rg * 4 + 2][hc] = fminf(fmaxf(acc2, 0.0f), 6.0f);
        hs[rg * 4 + 3][hc] = fminf(fmaxf(acc3, 0.0f), 6.0f);
    }
    __syncthreads();

    {
        int col = t;
        float acc[16];
        float bb = b2[col];
#pragma unroll
        for (int r = 0; r < 16; r++) acc[r] = bb;
        for (int k = 0; k < 64; k++) {
            float w = W2[k * 256 + col];
#pragma unroll
            for (int r = 0; r < 16; r++) acc[r] = fmaf(hs[r][k], w, acc[r]);
        }
#pragma unroll
        for (int r = 0; r < 16; r++) {
            float u = acc[r];
            float act = u * __saturatef((u + 3.0f) * (1.0f / 6.0f));
            size_t idx = (size_t)(row0 + r) * Dd + col;
            out[idx] = fmaf(act, xs[r][col], v[idx]);
        }
    }
}

// ---------------- launch ----------------
extern "C" void kernel_launch(void* const* d_in, const int* in_sizes, int n_in,
                              void* d_out, int out_size) {
    const float* v     = (const float*)d_in[0];
    const float* WQ    = (const float*)d_in[1];
    const float* bQ    = (const float*)d_in[2];
    const float* WK    = (const float*)d_in[3];
    const float* bK    = (const float*)d_in[4];
    const float* WV    = (const float*)d_in[5];
    const float* bV    = (const float*)d_in[6];
    const float* Wo    = (const float*)d_in[7];
    const float* bo    = (const float*)d_in[8];
    const float* W1    = (const float*)d_in[9];
    const float* b1    = (const float*)d_in[10];
    const float* W2    = (const float*)d_in[11];
    const float* b2    = (const float*)d_in[12];
    const float* gamma = (const float*)d_in[13];
    const float* beta  = (const float*)d_in[14];
    const int*   src   = (const int*)d_in[15];
    const int*   dst   = (const int*)d_in[16];
    float* out = (float*)d_out;

    cudaStream_t s2 = g_ss.s2;

    k_zero<<<(Nn + 255) / 256, 256>>>();
    k_count<<<(Ee + 255) / 256, 256>>>(src, dst);
    k_scan<<<SCANB, 256>>>();
    cudaEventRecord(g_ss.ev_scan, 0);

    // side stream: scatter (only consumer is k_agg) — overlaps prep + QKV GEMM
    cudaStreamWaitEvent(s2, g_ss.ev_scan, 0);
    k_scatter<<<(Ee + 255) / 256, 256, 0, s2>>>(src, dst);
    cudaEventRecord(g_ss.ev_s2, s2);

    // main stream continues
    k_prep<<<256 + (Nn * Dd / 4 + 255) / 256, 256>>>(v, WQ, WK, WV, Wo);
    k_gemm_bf16<0><<<dim3(2, 79, 3), 256>>>(bQ, bK, bV);

    cudaStreamWaitEvent(0, g_ss.ev_s2, 0);
    k_agg<<<1250, 256>>>();

    k_gemm_bf16<1><<<dim3(2, 79, 1), 256>>>(bo, nullptr, nullptr);

    k_se<<<Nn / 16, 256>>>(gamma, beta, W1, b1, W2, b2, v, out);
}

// round 17
// speedup vs baseline: 1.0719x; 1.0146x over previous
#include <cuda_runtime.h>
#include <cuda_bf16.h>
#include <math.h>

#define Nn 10000
#define Ee 320000
#define Dd 256
#define Hh 4
#define BN_EPS 1e-5f
#define MROWS 10112   // 79 * 128 padded rows
#define SCANB 40      // scan blocks (40*256 >= Nn)

// ---------------- scratch (device globals; .bss zero on load, re-zeroed by the
// tails of k_agg/k_se each run so every graph replay starts identically) ----------
__device__ int   g_cin[Nn];
__device__ int   g_cout[Nn];
__device__ int   g_off[Nn + 1];
__device__ int   g_fill[Nn];
__device__ int   g_csrc[Ee];
__device__ int   g_bsum[SCANB];
__device__ int   g_flag;
__device__ int   g_maxdeg;
__device__ float g_sumexp;
__device__ float g_ex[Nn];
__device__ __nv_bfloat16 g_mVh[MROWS * Dd];  // bf16 center-scaled mV (row-major)
__device__ float g_q[MROWS * Dd];            // fp32 q
__device__ __nv_bfloat16 g_kh[MROWS * Dd];   // bf16 k
__device__ __nv_bfloat16 g_vh[MROWS * Dd];   // bf16 vv
__device__ __nv_bfloat16 g_wv[MROWS * Dd];   // bf16 normalized wv (row-major)
__device__ float g_o[MROWS * Dd];
__device__ __nv_bfloat16 g_Wth[4 * Dd * Dd]; // bf16 transposed weights [z][n][k]
__device__ float g_bnsum[Dd];
__device__ float g_bnss[Dd];

// ---------------- side stream + events (created at load) ----------------
struct SideStream {
    cudaStream_t s2;
    cudaEvent_t ev_scan, ev_s2;
    SideStream() {
        cudaStreamCreateWithFlags(&s2, cudaStreamNonBlocking);
        cudaEventCreateWithFlags(&ev_scan, cudaEventDisableTiming);
        cudaEventCreateWithFlags(&ev_s2, cudaEventDisableTiming);
    }
};
static SideStream g_ss;

// ---------------- 1: in/out degree histograms (counters pre-zeroed by k_se tail) ---
__global__ void k_count(const int* __restrict__ src, const int* __restrict__ dst) {
    int e = blockIdx.x * blockDim.x + threadIdx.x;
    if (e < Ee) {
        atomicAdd(&g_cout[src[e]], 1);
        atomicAdd(&g_cin[dst[e]], 1);
    }
}

// ---------------- 1b: fused scan + softmax prep (single kernel, flag-based sync) ---
__global__ void __launch_bounds__(256) k_scan() {
    __shared__ int wsum[8];
    __shared__ int wmax[8];
    __shared__ float wred[8];
    __shared__ int pre_s;
    int t = threadIdx.x;
    int lane = t & 31, w = t >> 5;
    int bid = blockIdx.x;
    int n = bid * 256 + t;
    int ci = (n < Nn) ? g_cin[n] : 0;
    int co = (n < Nn) ? g_cout[n] : 0;
    int deg = ci + co;

    int x = ci;
#pragma unroll
    for (int o = 1; o < 32; o <<= 1) {
        int y = __shfl_up_sync(0xffffffffu, x, o);
        if (lane >= o) x += y;
    }
    int m = deg;
#pragma unroll
    for (int o = 16; o > 0; o >>= 1) m = max(m, __shfl_xor_sync(0xffffffffu, m, o));

    if (lane == 31) wsum[w] = x;
    if (lane == 0) wmax[w] = m;
    __syncthreads();
    if (w == 0) {
        int v = (lane < 8) ? wsum[lane] : 0;
#pragma unroll
        for (int o = 1; o < 8; o <<= 1) {
            int y = __shfl_up_sync(0xffffffffu, v, o);
            if (lane >= o) v += y;
        }
        if (lane < 8) wsum[lane] = v;
        int mm = (lane < 8) ? wmax[lane] : 0;
#pragma unroll
        for (int o = 4; o > 0; o >>= 1) mm = max(mm, __shfl_xor_sync(0xffffffffu, mm, o));
        if (lane == 0) {
            atomicMax(&g_maxdeg, mm);
            g_bsum[bid] = wsum[7];
            __threadfence();
            atomicAdd(&g_flag, 1);
        }
    }
    if (t == 0) {
        while (atomicAdd(&g_flag, 0) < SCANB) { }
    }
    __syncthreads();

    if (t < 32) {
        int v = (t < bid) ? g_bsum[t] : 0;
        if (t + 32 < bid) v += g_bsum[t + 32];
#pragma unroll
        for (int o = 16; o > 0; o >>= 1) v += __shfl_xor_sync(0xffffffffu, v, o);
        if (t == 0) pre_s = v;
    }
    __syncthreads();

    int wpre = (w > 0) ? wsum[w - 1] : 0;
    int off = pre_s + wpre + x - ci;
    int maxdeg = g_maxdeg;
    float ex = 0.0f;
    if (n < Nn) {
        g_off[n] = off;
        g_fill[n] = off;
        ex = expf((float)(deg - maxdeg));
        g_ex[n] = ex;
    }
    if (bid == 0 && t == 0) g_off[Nn] = Ee;

    float s = ex;
#pragma unroll
    for (int o = 16; o > 0; o >>= 1) s += __shfl_xor_sync(0xffffffffu, s, o);
    if (lane == 0) wred[w] = s;
    __syncthreads();
    if (w == 0) {
        float v = (lane < 8) ? wred[lane] : 0.0f;
#pragma unroll
        for (int o = 4; o > 0; o >>= 1) v += __shfl_xor_sync(0xffffffffu, v, o);
        if (lane == 0) atomicAdd(&g_sumexp, v);
    }
}

// ---------------- 1c: scatter src ids into CSR order ----------------
__global__ void k_scatter(const int* __restrict__ src, const int* __restrict__ dst) {
    int e = blockIdx.x * blockDim.x + threadIdx.x;
    if (e < Ee) {
        int d = dst[e];
        int pos = atomicAdd(&g_fill[d], 1);
        g_csrc[pos] = src[e];
    }
}

// ---------------- 2: fused prep — weight transpose (blocks 0..255) + mv (rest) -----
__global__ void __launch_bounds__(256) k_prep(const float* __restrict__ v,
                                              const float* __restrict__ WQ,
                                              const float* __restrict__ WK,
                                              const float* __restrict__ WV,
                                              const float* __restrict__ Wo) {
    int b = blockIdx.x;
    if (b < 256) {
        __shared__ float tl[32][33];
        int z = b >> 6;
        int idx = b & 63;
        int k0 = (idx & 7) * 32, n0 = (idx >> 3) * 32;
        const float* W = (z == 0) ? WQ : (z == 1) ? WK : (z == 2) ? WV : Wo;
        int tx = threadIdx.x & 31, ty = threadIdx.x >> 5;
#pragma unroll
        for (int j = 0; j < 32; j += 8)
            tl[ty + j][tx] = W[(size_t)(k0 + ty + j) * Dd + n0 + tx];
        __syncthreads();
#pragma unroll
        for (int j = 0; j < 32; j += 8)
            g_Wth[(size_t)z * Dd * Dd + (size_t)(n0 + ty + j) * Dd + k0 + tx] =
                __float2bfloat16(tl[tx][ty + j]);
    } else {
        int i4 = (b - 256) * 256 + threadIdx.x;
        if (i4 >= Nn * Dd / 4) return;
        int n = i4 >> 6;
        float c = g_ex[n] / g_sumexp;
        float4 a = ((const float4*)v)[i4];
        __nv_bfloat162 p0 = __float22bfloat162_rn(make_float2(a.x * c, a.y * c));
        __nv_bfloat162 p1 = __float22bfloat162_rn(make_float2(a.z * c, a.w * c));
        __nv_bfloat162* o = (__nv_bfloat162*)g_mVh;
        o[i4 * 2]     = p0;
        o[i4 * 2 + 1] = p1;
    }
}

// ---------------- cp.async helpers ----------------
__device__ __forceinline__ void cpa16(void* s, const void* g) {
    unsigned sa = (unsigned)__cvta_generic_to_shared(s);
    asm volatile("cp.async.ca.shared.global [%0], [%1], 16;" :: "r"(sa), "l"(g));
}
__device__ __forceinline__ void cp_commit() { asm volatile("cp.async.commit_group;"); }
__device__ __forceinline__ void cp_wait1() { asm volatile("cp.async.wait_group 1;"); }

__device__ __forceinline__ void mma16(float* c, const unsigned* a, const unsigned* b) {
    asm volatile(
        "mma.sync.aligned.m16n8k16.row.col.f32.bf16.bf16.f32 "
        "{%0,%1,%2,%3},{%4,%5,%6,%7},{%8,%9},{%0,%1,%2,%3};"
        : "+f"(c[0]), "+f"(c[1]), "+f"(c[2]), "+f"(c[3])
        : "r"(a[0]), "r"(a[1]), "r"(a[2]), "r"(a[3]), "r"(b[0]), "r"(b[1]));
}

// ---------------- 4: bf16 tensor-core GEMM, 3-stage cp.async, 2 CTAs/SM -----------
template <int MODE>
__global__ void __launch_bounds__(256, 2) k_gemm_bf16(
    const float* __restrict__ ba, const float* __restrict__ bb, const float* __restrict__ bc) {
    __shared__ __nv_bfloat16 As[3][128 * 40];
    __shared__ __nv_bfloat16 Bs[3][128 * 40];

    const int zsel = (MODE == 0) ? blockIdx.z : 3;
    const __nv_bfloat16* A = (MODE == 0) ? g_mVh : g_wv;
    const __nv_bfloat16* B = g_Wth + (size_t)zsel * Dd * Dd;
    const float* bias = (MODE == 1) ? ba : (zsel == 0) ? ba : (zsel == 1) ? bb : bc;

    const int tid = threadIdx.x;
    const int lane = tid & 31;
    const int warp = tid >> 5;
    const int wm = warp & 1;
    const int wn = warp >> 1;
    const int gid = lane >> 2;
    const int tig = lane & 3;
    const int bm = blockIdx.y * 128;
    const int bn = blockIdx.x * 128;

    const int lrow0 = tid >> 2;
    const int lcol0 = (tid & 3) * 8;
    const int lrow1 = (tid + 256) >> 2;
    const int lcol1 = lcol0;

    float acc[4][4][4];
#pragma unroll
    for (int i = 0; i < 4; i++)
#pragma unroll
        for (int j = 0; j < 4; j++)
#pragma unroll
            for (int q = 0; q < 4; q++) acc[i][j][q] = 0.0f;

#pragma unroll
    for (int st = 0; st < 2; st++) {
        int k0 = st * 32;
        cpa16(&As[st][lrow0 * 40 + lcol0], A + (size_t)(bm + lrow0) * Dd + k0 + lcol0);
        cpa16(&As[st][lrow1 * 40 + lcol1], A + (size_t)(bm + lrow1) * Dd + k0 + lcol1);
        cpa16(&Bs[st][lrow0 * 40 + lcol0], B + (size_t)(bn + lrow0) * Dd + k0 + lcol0);
        cpa16(&Bs[st][lrow1 * 40 + lcol1], B + (size_t)(bn + lrow1) * Dd + k0 + lcol1);
        cp_commit();
    }

#pragma unroll
    for (int ks = 0; ks < 8; ks++) {
        cp_wait1();
        __syncthreads();
        if (ks < 6) {
            int st = (ks + 2) % 3;
            int k0 = (ks + 2) * 32;
            cpa16(&As[st][lrow0 * 40 + lcol0], A + (size_t)(bm + lrow0) * Dd + k0 + lcol0);
            cpa16(&As[st][lrow1 * 40 + lcol1], A + (size_t)(bm + lrow1) * Dd + k0 + lcol1);
            cpa16(&Bs[st][lrow0 * 40 + lcol0], B + (size_t)(bn + lrow0) * Dd + k0 + lcol0);
            cpa16(&Bs[st][lrow1 * 40 + lcol1], B + (size_t)(bn + lrow1) * Dd + k0 + lcol1);
        }
        cp_commit();
        const __nv_bfloat16* as = As[ks % 3];
        const __nv_bfloat16* bs = Bs[ks % 3];
#pragma unroll
        for (int kk = 0; kk < 2; kk++) {
            int kb = kk * 16 + 2 * tig;
            unsigned af[4][4];
#pragma unroll
            for (int fm = 0; fm < 4; fm++) {
                int mrow = wm * 64 + fm * 16 + gid;
                af[fm][0] = *(const unsigned*)&as[mrow * 40 + kb];
                af[fm][1] = *(const unsigned*)&as[(mrow + 8) * 40 + kb];
                af[fm][2] = *(const unsigned*)&as[mrow * 40 + kb + 8];
                af[fm][3] = *(const unsigned*)&as[(mrow + 8) * 40 + kb + 8];
            }
            unsigned bfr[4][2];
#pragma unroll
            for (int fn = 0; fn < 4; fn++) {
                int nrow = wn * 32 + fn * 8 + gid;
                bfr[fn][0] = *(const unsigned*)&bs[nrow * 40 + kb];
                bfr[fn][1] = *(const unsigned*)&bs[nrow * 40 + kb + 8];
            }
#pragma unroll
            for (int fm = 0; fm < 4; fm++)
#pragma unroll
                for (int fn = 0; fn < 4; fn++)
                    mma16(acc[fm][fn], af[fm], bfr[fn]);
        }
    }

#pragma unroll
    for (int fn = 0; fn < 4; fn++) {
        int gc = bn + wn * 32 + fn * 8 + 2 * tig;
        float bv0 = bias[gc], bv1 = bias[gc + 1];
        float cs0 = 0.f, cs1 = 0.f, cq0 = 0.f, cq1 = 0.f;
#pragma unroll
        for (int fm = 0; fm < 4; fm++) {
            int gr = bm + wm * 64 + fm * 16 + gid;
            float2 o0 = make_float2(acc[fm][fn][0] + bv0, acc[fm][fn][1] + bv1);
            float2 o1 = make_float2(acc[fm][fn][2] + bv0, acc[fm][fn][3] + bv1);
            if (MODE == 1 || zsel == 0) {
                float* C = (MODE == 1) ? g_o : g_q;
                *(float2*)(C + (size_t)gr * Dd + gc) = o0;
                *(float2*)(C + (size_t)(gr + 8) * Dd + gc) = o1;
            } else {
                __nv_bfloat162* Ch = (__nv_bfloat162*)((zsel == 1) ? g_kh : g_vh);
                Ch[(size_t)gr * (Dd / 2) + (gc >> 1)] = __float22bfloat162_rn(o0);
                Ch[(size_t)(gr + 8) * (Dd / 2) + (gc >> 1)] = __float22bfloat162_rn(o1);
            }
            if (MODE == 1) {
                if (gr < Nn) {
                    cs0 += o0.x; cs1 += o0.y;
                    cq0 = fmaf(o0.x, o0.x, cq0); cq1 = fmaf(o0.y, o0.y, cq1);
                }
                if (gr + 8 < Nn) {
                    cs0 += o1.x; cs1 += o1.y;
                    cq0 = fmaf(o1.x, o1.x, cq0); cq1 = fmaf(o1.y, o1.y, cq1);
                }
            }
        }
        if (MODE == 1) {
#pragma unroll
            for (int o = 4; o <= 16; o <<= 1) {
                cs0 += __shfl_xor_sync(0xffffffffu, cs0, o);
                cs1 += __shfl_xor_sync(0xffffffffu, cs1, o);
                cq0 += __shfl_xor_sync(0xffffffffu, cq0, o);
                cq1 += __shfl_xor_sync(0xffffffffu, cq1, o);
            }
            if (gid == 0) {
                asm volatile("red.global.add.v2.f32 [%0], {%1,%2};"
                             :: "l"(&g_bnsum[gc]), "f"(cs0), "f"(cs1) : "memory");
                asm volatile("red.global.add.v2.f32 [%0], {%1,%2};"
                             :: "l"(&g_bnss[gc]), "f"(cq0), "f"(cq1) : "memory");
            }
        }
    }
}

// ---------------- bf16 helpers for aggregation ----------------
__device__ __forceinline__ float dot8(uint4 kx, float4 q0, float4 q1) {
    float2 p0 = __bfloat1622float2(*(__nv_bfloat162*)&kx.x);
    float2 p1 = __bfloat1622float2(*(__nv_bfloat162*)&kx.y);
    float2 p2 = __bfloat1622float2(*(__nv_bfloat162*)&kx.z);
    float2 p3 = __bfloat1622float2(*(__nv_bfloat162*)&kx.w);
    float d = p0.x * q0.x;
    d = fmaf(p0.y, q0.y, d);
    d = fmaf(p1.x, q0.z, d);
    d = fmaf(p1.y, q0.w, d);
    d = fmaf(p2.x, q1.x, d);
    d = fmaf(p2.y, q1.y, d);
    d = fmaf(p3.x, q1.z, d);
    d = fmaf(p3.y, q1.w, d);
    return d;
}

__device__ __forceinline__ void fma8(float4& a, float4& b, uint4 vx, float s) {
    float2 p0 = __bfloat1622float2(*(__nv_bfloat162*)&vx.x);
    float2 p1 = __bfloat1622float2(*(__nv_bfloat162*)&vx.y);
    float2 p2 = __bfloat1622float2(*(__nv_bfloat162*)&vx.z);
    float2 p3 = __bfloat1622float2(*(__nv_bfloat162*)&vx.w);
    a.x = fmaf(p0.x, s, a.x); a.y = fmaf(p0.y, s, a.y);
    a.z = fmaf(p1.x, s, a.z); a.w = fmaf(p1.y, s, a.w);
    b.x = fmaf(p2.x, s, b.x); b.y = fmaf(p2.y, s, b.y);
    b.z = fmaf(p3.x, s, b.z); b.w = fmaf(p3.y, s, b.w);
}

// ---------------- 5: CSR aggregation (block 0 re-zeroes BN accumulators) ----------
__global__ void __launch_bounds__(256) k_agg() {
    int tid = threadIdx.x;
    if (blockIdx.x == 0) {   // k_agg fully precedes gemm1 in stream order
        g_bnsum[tid] = 0.0f;
        g_bnss[tid] = 0.0f;
    }
    int lane = tid & 31;
    int w = tid >> 5;
    int n = blockIdx.x * 8 + w;
    int grp0 = lane & ~7;

    const float4* qr = (const float4*)(g_q + (size_t)n * Dd);
    float4 q0 = qr[lane * 2], q1 = qr[lane * 2 + 1];
    float4 accA = make_float4(0.f, 0.f, 0.f, 0.f);
    float4 accB = make_float4(0.f, 0.f, 0.f, 0.f);
    float z = 0.0f;
    int e = g_off[n];
    const int end = g_off[n + 1];
    const char* kbase = (const char*)g_kh;
    const char* vbase = (const char*)g_vh;
    const size_t loff = (size_t)lane * 16;

    int pn0 = 0, pn1 = 0, pn2 = 0, pn3 = 0;
    if (e + 4 <= end) {
        pn0 = g_csrc[e]; pn1 = g_csrc[e + 1];
        pn2 = g_csrc[e + 2]; pn3 = g_csrc[e + 3];
    }
    for (; e + 4 <= end; ) {
        int s0 = pn0, s1 = pn1, s2 = pn2, s3 = pn3;
        int e2 = e + 4;
        uint4 k0 = *(const uint4*)(kbase + (size_t)s0 * 512 + loff);
        uint4 k1 = *(const uint4*)(kbase + (size_t)s1 * 512 + loff);
        uint4 k2 = *(const uint4*)(kbase + (size_t)s2 * 512 + loff);
        uint4 k3 = *(const uint4*)(kbase + (size_t)s3 * 512 + loff);
        uint4 v0 = *(const uint4*)(vbase + (size_t)s0 * 512 + loff);
        uint4 v1 = *(const uint4*)(vbase + (size_t)s1 * 512 + loff);
        uint4 v2 = *(const uint4*)(vbase + (size_t)s2 * 512 + loff);
        uint4 v3 = *(const uint4*)(vbase + (size_t)s3 * 512 + loff);
        if (e2 + 4 <= end) {
            pn0 = g_csrc[e2]; pn1 = g_csrc[e2 + 1];
            pn2 = g_csrc[e2 + 2]; pn3 = g_csrc[e2 + 3];
        }
        float d0 = dot8(k0, q0, q1);
        float d1 = dot8(k1, q0, q1);
        float d2 = dot8(k2, q0, q1);
        float d3 = dot8(k3, q0, q1);
        d0 += __shfl_down_sync(0xffffffffu, d0, 4, 8);
        d1 += __shfl_down_sync(0xffffffffu, d1, 4, 8);
        d2 += __shfl_down_sync(0xffffffffu, d2, 4, 8);
        d3 += __shfl_down_sync(0xffffffffu, d3, 4, 8);
        d0 += __shfl_down_sync(0xffffffffu, d0, 2, 8);
        d1 += __shfl_down_sync(0xffffffffu, d1, 2, 8);
        d2 += __shfl_down_sync(0xffffffffu, d2, 2, 8);
        d3 += __shfl_down_sync(0xffffffffu, d3, 2, 8);
        d0 += __shfl_down_sync(0xffffffffu, d0, 1, 8);
        d1 += __shfl_down_sync(0xffffffffu, d1, 1, 8);
        d2 += __shfl_down_sync(0xffffffffu, d2, 1, 8);
        d3 += __shfl_down_sync(0xffffffffu, d3, 1, 8);
        d0 = __shfl_sync(0xffffffffu, d0, grp0);
        d1 = __shfl_sync(0xffffffffu, d1, grp0);
        d2 = __shfl_sync(0xffffffffu, d2, grp0);
        d3 = __shfl_sync(0xffffffffu, d3, grp0);
        float sv0 = __expf(fminf(fmaxf(d0 * 0.125f, -5.0f), 5.0f));
        float sv1 = __expf(fminf(fmaxf(d1 * 0.125f, -5.0f), 5.0f));
        float sv2 = __expf(fminf(fmaxf(d2 * 0.125f, -5.0f), 5.0f));
        float sv3 = __expf(fminf(fmaxf(d3 * 0.125f, -5.0f), 5.0f));
        z += (sv0 + sv1) + (sv2 + sv3);
        fma8(accA, accB, v0, sv0);
        fma8(accA, accB, v1, sv1);
        fma8(accA, accB, v2, sv2);
        fma8(accA, accB, v3, sv3);
        e = e2;
    }
    for (; e < end; e++) {
        int s0 = g_csrc[e];
        uint4 k0 = *(const uint4*)(kbase + (size_t)s0 * 512 + loff);
        uint4 v0 = *(const uint4*)(vbase + (size_t)s0 * 512 + loff);
        float d0 = dot8(k0, q0, q1);
        d0 += __shfl_down_sync(0xffffffffu, d0, 4, 8);
        d0 += __shfl_down_sync(0xffffffffu, d0, 2, 8);
        d0 += __shfl_down_sync(0xffffffffu, d0, 1, 8);
        d0 = __shfl_sync(0xffffffffu, d0, grp0);
        float sv0 = __expf(fminf(fmaxf(d0 * 0.125f, -5.0f), 5.0f));
        z += sv0;
        fma8(accA, accB, v0, sv0);
    }
    float inv = 1.0f / z;
    uint4 pk;
    __nv_bfloat162 b0 = __float22bfloat162_rn(make_float2(accA.x * inv, accA.y * inv));
    __nv_bfloat162 b1 = __float22bfloat162_rn(make_float2(accA.z * inv, accA.w * inv));
    __nv_bfloat162 b2 = __float22bfloat162_rn(make_float2(accB.x * inv, accB.y * inv));
    __nv_bfloat162 b3 = __float22bfloat162_rn(make_float2(accB.z * inv, accB.w * inv));
    pk.x = *(unsigned*)&b0; pk.y = *(unsigned*)&b1;
    pk.z = *(unsigned*)&b2; pk.w = *(unsigned*)&b3;
    *(uint4*)((char*)g_wv + (size_t)n * 512 + loff) = pk;
}

// ---------------- 7: fused BN + ReLU6 + SE + hardswish + residual + counter reset --
__global__ void __launch_bounds__(256) k_se(const float* __restrict__ gamma,
                                            const float* __restrict__ beta,
                                            const float* __restrict__ W1,
                                            const float* __restrict__ b1,
                                            const float* __restrict__ W2,
                                            const float* __restrict__ b2,
                                            const float* __restrict__ v,
                                            float* __restrict__ out) {
    __shared__ float xs[16][256];
    __shared__ float hs[16][64];
    __shared__ float sa[256], sb[256];
    int t = threadIdx.x;
    int row0 = blockIdx.x * 16;

    // reset counters for next graph replay (each block owns its 16 nodes)
    if (t < 16) {
        g_cin[row0 + t] = 0;
        g_cout[row0 + t] = 0;
    }
    if (blockIdx.x == 0 && t == 0) {
        g_flag = 0;
        g_maxdeg = 0;
        g_sumexp = 0.0f;
    }

    {
        float mean = g_bnsum[t] * (1.0f / Nn);
        float var = g_bnss[t] * (1.0f / Nn) - mean * mean;
        float istd = rsqrtf(var + BN_EPS);
        float a = gamma[t] * istd;
        sa[t] = a;
        sb[t] = beta[t] - mean * a;
    }
    __syncthreads();

    for (int i = t; i < 16 * 256; i += 256) {
        int r = i >> 8, c = i & 255;
        float xv = fmaf(sa[c], g_o[(size_t)(row0 + r) * Dd + c], sb[c]);
        xs[r][c] = fminf(fmaxf(xv, 0.0f), 6.0f);
    }
    __syncthreads();

    {
        int hc = t & 63, rg = t >> 6;
        float acc0 = b1[hc], acc1 = acc0, acc2 = acc0, acc3 = acc0;
        for (int k = 0; k < 256; k++) {
            float w = W1[k * 64 + hc];
            acc0 = fmaf(xs[rg * 4 + 0][k], w, acc0);
            acc1 = fmaf(xs[rg * 4 + 1][k], w, acc1);
            acc2 = fmaf(xs[rg * 4 + 2][k], w, acc2);
            acc3 = fmaf(xs[rg * 4 + 3][k], w, acc3);
        }
        hs[rg * 4 + 0][hc] = fminf(fmaxf(acc0, 0.0f), 6.0f);
        hs[rg * 4 + 1][hc] = fminf(fmaxf(acc1, 0.0f), 6.0f);
        hs[rg * 4 + 2][hc] = fminf(fmaxf(acc2, 0.0f), 6.0f);
        hs[rg * 4 + 3][hc] = fminf(fmaxf(acc3, 0.0f), 6.0f);
    }
    __syncthreads();

    {
        int col = t;
        float acc[16];
        float bb = b2[col];
#pragma unroll
        for (int r = 0; r < 16; r++) acc[r] = bb;
        for (int k = 0; k < 64; k++) {
            float w = W2[k * 256 + col];
#pragma unroll
            for (int r = 0; r < 16; r++) acc[r] = fmaf(hs[r][k], w, acc[r]);
        }
#pragma unroll
        for (int r = 0; r < 16; r++) {
            float u = acc[r];
            float act = u * __saturatef((u + 3.0f) * (1.0f / 6.0f));
            size_t idx = (size_t)(row0 + r) * Dd + col;
            out[idx] = fmaf(act, xs[r][col], v[idx]);
        }
    }
}

// ---------------- launch ----------------
extern "C" void kernel_launch(void* const* d_in, const int* in_sizes, int n_in,
                              void* d_out, int out_size) {
    const float* v     = (const float*)d_in[0];
    const float* WQ    = (const float*)d_in[1];
    const float* bQ    = (const float*)d_in[2];
    const float* WK    = (const float*)d_in[3];
    const float* bK    = (const float*)d_in[4];
    const float* WV    = (const float*)d_in[5];
    const float* bV    = (const float*)d_in[6];
    const float* Wo    = (const float*)d_in[7];
    const float* bo    = (const float*)d_in[8];
    const float* W1    = (const float*)d_in[9];
    const float* b1    = (const float*)d_in[10];
    const float* W2    = (const float*)d_in[11];
    const float* b2    = (const float*)d_in[12];
    const float* gamma = (const float*)d_in[13];
    const float* beta  = (const float*)d_in[14];
    const int*   src   = (const int*)d_in[15];
    const int*   dst   = (const int*)d_in[16];
    float* out = (float*)d_out;

    cudaStream_t s2 = g_ss.s2;

    k_count<<<(Ee + 255) / 256, 256>>>(src, dst);
    k_scan<<<SCANB, 256>>>();
    cudaEventRecord(g_ss.ev_scan, 0);

    // side stream: scatter (only consumer is k_agg) — overlaps prep + QKV GEMM
    cudaStreamWaitEvent(s2, g_ss.ev_scan, 0);
    k_scatter<<<(Ee + 255) / 256, 256, 0, s2>>>(src, dst);
    cudaEventRecord(g_ss.ev_s2, s2);

    // main stream continues
    k_prep<<<256 + (Nn * Dd / 4 + 255) / 256, 256>>>(v, WQ, WK, WV, Wo);
    k_gemm_bf16<0><<<dim3(2, 79, 3), 256>>>(bQ, bK, bV);

    cudaStreamWaitEvent(0, g_ss.ev_s2, 0);
    k_agg<<<1250, 256>>>();

    k_gemm_bf16<1><<<dim3(2, 79, 1), 256>>>(bo, nullptr, nullptr);

    k_se<<<Nn / 16, 256>>>(gamma, beta, W1, b1, W2, b2, v, out);
}